// round 15
// baseline (speedup 1.0000x reference)
#include <cuda_runtime.h>
#include <cuda_fp16.h>
#include <cstdint>

#define BB 2
#define SS 2048
#define DD 1024
#define HH 16
#define HD 64
#define SCALE 0.03125f   // 1/sqrt(1024)
#define MT   4096        // B*S total rows
#define LOG2E 1.44269504f

// ---------------- scratch (no allocation allowed) ----------------
__device__ __half g_Q [(size_t)BB*HH*SS*HD];   // Q single fp16 (pre-scaled)
__device__ __half g_Kh[(size_t)BB*HH*SS*HD];   // K single fp16
__device__ float  g_V [(size_t)BB*HH*SS*HD];   // fp32 staging [bh][s][e]
__device__ __half g_Vt[(size_t)BB*HH*HD*SS];   // V^T single fp16 [bh][e][s]
__device__ __half g_Xh[(size_t)MT*DD];
__device__ __half g_Xl[(size_t)MT*DD];
__device__ __half g_Ah[(size_t)MT*DD];
__device__ __half g_Al[(size_t)MT*DD];
// qkv weights, pre-transposed, single fp16: [w(q,k,v)][h][n=HD][k=DD]
__device__ __half g_W[(size_t)3*HH*HD*DD];
__device__ __half g_P[(size_t)DD*DD];          // Wp [j][k] single fp16

__device__ __forceinline__ uint32_t h2u(__half2 v) {
    return *reinterpret_cast<uint32_t*>(&v);
}
__device__ __forceinline__ uint32_t s2u(const void* p) {
    uint32_t a;
    asm("{ .reg .u64 t; cvta.to.shared.u64 t, %1; cvt.u32.u64 %0, t; }" : "=r"(a) : "l"(p));
    return a;
}
__device__ __forceinline__ void cpa16(uint32_t dst, const void* src) {
    asm volatile("cp.async.ca.shared.global [%0], [%1], 16;" :: "r"(dst), "l"(src));
}
__device__ __forceinline__ void mma16816(float* d, const uint32_t* a, const uint32_t* b) {
    asm volatile(
        "mma.sync.aligned.m16n8k16.row.col.f32.f16.f16.f32 "
        "{%0,%1,%2,%3},{%4,%5,%6,%7},{%8,%9},{%0,%1,%2,%3};"
        : "+f"(d[0]), "+f"(d[1]), "+f"(d[2]), "+f"(d[3])
        : "r"(a[0]), "r"(a[1]), "r"(a[2]), "r"(a[3]), "r"(b[0]), "r"(b[1]));
}
__device__ __forceinline__ void ldsm4(uint32_t* r, uint32_t a) {
    asm volatile("ldmatrix.sync.aligned.m8n8.x4.shared.b16 {%0,%1,%2,%3}, [%4];"
                 : "=r"(r[0]), "=r"(r[1]), "=r"(r[2]), "=r"(r[3]) : "r"(a));
}
__device__ __forceinline__ void split2(float f0, float f1, uint32_t& hi, uint32_t& lo) {
    __half2 h = __floats2half2_rn(f0, f1);
    __half2 l = __floats2half2_rn(f0 - __low2float(h), f1 - __high2float(h));
    hi = h2u(h); lo = h2u(l);
}

// ================= prep kernels =====================
__global__ __launch_bounds__(256) void prep_x(const float* __restrict__ x)
{
    size_t i = (size_t)blockIdx.x * 256 + threadIdx.x;
    float4 v = ((const float4*)x)[i];
    uint32_t h01, l01, h23, l23;
    split2(v.x, v.y, h01, l01);
    split2(v.z, v.w, h23, l23);
    ((uint2*)g_Xh)[i] = make_uint2(h01, h23);
    ((uint2*)g_Xl)[i] = make_uint2(l01, l23);
}

// Wq/Wk/Wv: [h][k=1024][n=64] -> g_W: [w][h][n][k] single fp16
__global__ __launch_bounds__(256) void prep_wqkv(
    const float* __restrict__ Wq, const float* __restrict__ Wk, const float* __restrict__ Wv)
{
    __shared__ float ws[64][65];
    const int k0t = blockIdx.x, h = blockIdx.y, w = blockIdx.z;
    const float* W = (w == 0 ? Wq : w == 1 ? Wk : Wv)
                     + (size_t)h * DD * HD + (size_t)k0t * 64 * HD;
    const int tid = threadIdx.x;
    #pragma unroll
    for (int i = 0; i < 4; i++) {
        int idx = tid + i * 256; int kk = idx >> 4, c4 = idx & 15;
        float4 v = *(const float4*)(W + (size_t)kk * HD + c4 * 4);
        ws[kk][c4*4+0] = v.x; ws[kk][c4*4+1] = v.y;
        ws[kk][c4*4+2] = v.z; ws[kk][c4*4+3] = v.w;
    }
    __syncthreads();
    __half* oh = g_W + ((size_t)(w * HH + h) * HD) * DD + k0t * 64;
    #pragma unroll
    for (int i = 0; i < 4; i++) {
        int idx = tid + i * 256; int n = idx >> 4, u = idx & 15;
        __half2 h01 = __floats2half2_rn(ws[u*4+0][n], ws[u*4+1][n]);
        __half2 h23 = __floats2half2_rn(ws[u*4+2][n], ws[u*4+3][n]);
        *(uint2*)(oh + (size_t)n * DD + u * 4) = make_uint2(h2u(h01), h2u(h23));
    }
}

__global__ __launch_bounds__(256) void prep_wp(const float* __restrict__ Wp)
{
    size_t i = (size_t)blockIdx.x * 256 + threadIdx.x;
    float4 v = ((const float4*)Wp)[i];
    __half2 h01 = __floats2half2_rn(v.x, v.y);
    __half2 h23 = __floats2half2_rn(v.z, v.w);
    ((uint2*)g_P)[i] = make_uint2(h2u(h01), h2u(h23));
}

// V fp32 [bh][s][e] -> transposed single fp16 g_Vt [bh][e][s]
__global__ __launch_bounds__(256) void vprep()
{
    __shared__ float ts[64][65];
    const int stile = blockIdx.x, bh = blockIdx.y;
    const int tid = threadIdx.x;
    const float* src = g_V + ((size_t)bh * SS + (size_t)stile * 64) * HD;
    #pragma unroll
    for (int i = 0; i < 4; i++) {
        int idx = tid + i * 256; int row = idx >> 4, c4 = idx & 15;
        float4 v = *(const float4*)(src + (size_t)row * HD + c4 * 4);
        ts[row][c4*4+0] = v.x; ts[row][c4*4+1] = v.y;
        ts[row][c4*4+2] = v.z; ts[row][c4*4+3] = v.w;
    }
    __syncthreads();
    #pragma unroll
    for (int i = 0; i < 4; i++) {
        int idx = tid + i * 256; int e = idx >> 4, c4 = idx & 15;
        __half2 h01 = __floats2half2_rn(ts[c4*4+0][e], ts[c4*4+1][e]);
        __half2 h23 = __floats2half2_rn(ts[c4*4+2][e], ts[c4*4+3][e]);
        size_t d = ((size_t)bh * HD + e) * SS + (size_t)stile * 64 + c4 * 4;
        *(uint2*)(g_Vt + d) = make_uint2(h2u(h01), h2u(h23));
    }
}

// =============== GEMM smem layout: 2-stage pipeline ==========================
#define AST 72
#define ST_AH 0
#define ST_AL (128*AST)
#define ST_B  (2*128*AST)
#define ST_ELEMS (2*128*AST + 64*AST)   // 23040
#define GEMM_SMEM (2*ST_ELEMS*2)        // 92160 bytes

// ================= Kernel A: QKV GEMM ========================================
// Q,K: 1-term (Xh only). V: 2-term (Xh+Xl).
// grid (32 m-tiles, 48 n-tiles over {o,h}), block 256 (8 warps, 4m x 2n).
__global__ __launch_bounds__(256) void qkv_gemm(void)
{
    extern __shared__ __half sm[];
    const uint32_t sb = s2u(sm);
    const int tid = threadIdx.x, lane = tid & 31, wid = tid >> 5;
    const int wm = wid & 3, wn = wid >> 2;
    const int m0 = blockIdx.x * 128;
    const int nt = blockIdx.y;            // o = nt>>4, h = nt&15
    const int o = nt >> 4, h = nt & 15;
    const bool needAl = (o == 2);

    const __half* W = g_W + (size_t)nt * HD * DD;

    auto issue = [&](int c, int st) {
        const uint32_t base = sb + (uint32_t)st * (ST_ELEMS * 2);
        const int k0 = c * 64;
        #pragma unroll
        for (int i = 0; i < 4; i++) {
            int idx = tid + i * 256;
            int row = idx >> 3, qq = idx & 7;
            size_t go = (size_t)(m0 + row) * DD + k0 + qq * 8;
            uint32_t so = (uint32_t)(row * AST + qq * 8) * 2;
            cpa16(base + ST_AH * 2 + so, g_Xh + go);
            if (needAl) cpa16(base + ST_AL * 2 + so, g_Xl + go);
        }
        #pragma unroll
        for (int i = 0; i < 2; i++) {
            int idx = tid + i * 256;
            int row = idx >> 3, qq = idx & 7;
            size_t go = (size_t)row * DD + k0 + qq * 8;
            uint32_t so = (uint32_t)(row * AST + qq * 8) * 2;
            cpa16(base + ST_B * 2 + so, W + go);
        }
        asm volatile("cp.async.commit_group;" ::: "memory");
    };

    float d[2][4][4] = {};
    const int g = lane >> 2, t2 = (lane & 3) * 2;
    const int rr = lane & 7, q8 = lane >> 3;
    const int laneA = (rr + ((q8 & 1) ? 8 : 0)) * AST + ((q8 & 2) ? 8 : 0);
    const int laneB = (rr + ((q8 & 2) ? 8 : 0)) * AST + ((q8 & 1) ? 8 : 0);

    issue(0, 0);
    for (int c = 0; c < 16; c++) {
        const int st = c & 1;
        if (c < 15) {
            issue(c + 1, st ^ 1);
            asm volatile("cp.async.wait_group 1;" ::: "memory");
        } else {
            asm volatile("cp.async.wait_group 0;" ::: "memory");
        }
        __syncthreads();

        const uint32_t stb = sb + (uint32_t)st * (ST_ELEMS * 2);

        #pragma unroll
        for (int ka = 0; ka < 4; ka++) {
            uint32_t ah[2][4], al[2][4], bh[4][2];
            #pragma unroll
            for (int ma = 0; ma < 2; ma++) {
                uint32_t ao = stb + (uint32_t)(ST_AH + (wm*32 + ma*16)*AST + ka*16 + laneA) * 2;
                ldsm4(ah[ma], ao);
                if (needAl) ldsm4(al[ma], ao + (uint32_t)(ST_AL - ST_AH) * 2);
            }
            #pragma unroll
            for (int p = 0; p < 2; p++) {
                uint32_t bo = stb + (uint32_t)(ST_B + (wn*32 + p*16)*AST + ka*16 + laneB) * 2;
                uint32_t t[4];
                ldsm4(t, bo);
                bh[2*p][0] = t[0]; bh[2*p][1] = t[1]; bh[2*p+1][0] = t[2]; bh[2*p+1][1] = t[3];
            }
            #pragma unroll
            for (int ma = 0; ma < 2; ma++)
                #pragma unroll
                for (int na = 0; na < 4; na++) {
                    mma16816(d[ma][na], ah[ma], bh[na]);
                    if (needAl) mma16816(d[ma][na], al[ma], bh[na]);
                }
        }
        __syncthreads();
    }

    // epilogue: Q -> single fp16 (pre-scaled); K -> single fp16; V -> fp32
    const float sc = (o == 0) ? SCALE : 1.0f;
    #pragma unroll
    for (int ma = 0; ma < 2; ma++) {
        #pragma unroll
        for (int na = 0; na < 4; na++) {
            int col = wn * 32 + na * 8 + t2;
            int r0g = m0 + wm * 32 + ma * 16 + g;
            int b0 = r0g >> 11, s0 = r0g & 2047;
            int r1g = r0g + 8;
            int b1 = r1g >> 11, s1 = r1g & 2047;
            size_t a0 = (((size_t)(b0 * HH + h)) * SS + s0) * HD + col;
            size_t a1 = (((size_t)(b1 * HH + h)) * SS + s1) * HD + col;
            if (o == 2) {
                *(float2*)&g_V[a0] = make_float2(d[ma][na][0], d[ma][na][1]);
                *(float2*)&g_V[a1] = make_float2(d[ma][na][2], d[ma][na][3]);
            } else {
                __half* G = (o == 0) ? g_Q : g_Kh;
                __half2 h01 = __floats2half2_rn(d[ma][na][0] * sc, d[ma][na][1] * sc);
                __half2 h23 = __floats2half2_rn(d[ma][na][2] * sc, d[ma][na][3] * sc);
                *(uint32_t*)(G + a0) = h2u(h01);
                *(uint32_t*)(G + a1) = h2u(h23);
            }
        }
    }
}

// ================= Kernel B: flash attention ================================
// Q single fp16; QK 1-term; PV 2-term (P hi/lo).
// smem: Q (64x72 = 9216 B) + 2 stages x (K + V tiles, 18432 B) = 46080 B
#define QB       9216
#define KTILE_B  9216
#define ASTAGE_B 18432
#define ATT_SMEM (QB + 2*ASTAGE_B)

__global__ __launch_bounds__(128) void attn_mma()
{
    extern __shared__ __half smb[];
    const uint32_t sb = s2u(smb);
    const int tid = threadIdx.x, lane = tid & 31, wid = tid >> 5;
    const int g = lane >> 2, t2 = (lane & 3) * 2;
    const int qt = 31 - blockIdx.x;
    const int bh = blockIdx.y;
    const int r0w = wid * 16;

    const int rr = lane & 7, q8 = lane >> 3;
    const int laneA = (rr + ((q8 & 1) ? 8 : 0)) * AST + ((q8 & 2) ? 8 : 0);
    const int laneB = (rr + ((q8 & 2) ? 8 : 0)) * AST + ((q8 & 1) ? 8 : 0);

    __half* Qs = smb;

    // Q tile load: 64 rows x 8 uint4
    {
        const __half* sh = g_Q + ((size_t)bh * SS + (size_t)qt * 64) * HD;
        #pragma unroll
        for (int i = 0; i < 4; i++) {
            int idx = tid + i * 128; int row = idx >> 3, qq = idx & 7;
            *(uint4*)&Qs[row * AST + qq * 8] = *(const uint4*)(sh + (size_t)row * HD + qq * 8);
        }
    }

    auto issue = [&](int j, int st) {
        const uint32_t base = sb + QB + st * ASTAGE_B;
        const __half* kh = g_Kh + ((size_t)bh * SS + (size_t)j * 64) * HD;
        const __half* vv = g_Vt + (size_t)bh * HD * SS + (size_t)j * 64;
        #pragma unroll
        for (int i = 0; i < 4; i++) {
            int idx = tid + i * 128; int row = idx >> 3, qq = idx & 7;
            uint32_t so = (uint32_t)(row * AST + qq * 8) * 2;
            cpa16(base + so, kh + (size_t)row * HD + qq * 8);
            cpa16(base + KTILE_B + so, vv + (size_t)row * SS + qq * 8);
        }
        asm volatile("cp.async.commit_group;" ::: "memory");
    };

    float m0 = -1e30f, m1 = -1e30f, l0 = 0.f, l1 = 0.f;
    float o[8][4] = {};

    issue(0, 0);

    for (int j = 0; j <= qt; j++) {
        const int st = j & 1;
        if (j < qt) {
            issue(j + 1, st ^ 1);
            asm volatile("cp.async.wait_group 1;" ::: "memory");
        } else {
            asm volatile("cp.async.wait_group 0;" ::: "memory");
        }
        __syncthreads();

        const uint32_t kbB = sb + QB + st * ASTAGE_B;
        const uint32_t vbB = kbB + KTILE_B;

        // ---- S = Q @ K^T (1-term) ----
        float s[8][4] = {};
        #pragma unroll
        for (int ka = 0; ka < 4; ka++) {
            uint32_t qh[4];
            uint32_t qo = sb + (uint32_t)(r0w * AST + ka*16 + laneA) * 2;
            ldsm4(qh, qo);
            #pragma unroll
            for (int p = 0; p < 4; p++) {
                uint32_t off = (uint32_t)(p*16*AST + ka*16 + laneB) * 2;
                uint32_t th[4];
                ldsm4(th, kbB + off);
                mma16816(s[2*p],   qh, th);
                mma16816(s[2*p+1], qh, th + 2);
            }
        }

        if (j == qt) {
            const int row0 = r0w + g, row1 = row0 + 8;
            #pragma unroll
            for (int nt = 0; nt < 8; nt++) {
                int cb = nt * 8 + t2;
                if (cb     > row0) s[nt][0] = -1e30f;
                if (cb + 1 > row0) s[nt][1] = -1e30f;
                if (cb     > row1) s[nt][2] = -1e30f;
                if (cb + 1 > row1) s[nt][3] = -1e30f;
            }
        }

        float mt0 = -1e30f, mt1 = -1e30f;
        #pragma unroll
        for (int nt = 0; nt < 8; nt++) {
            mt0 = fmaxf(mt0, fmaxf(s[nt][0], s[nt][1]));
            mt1 = fmaxf(mt1, fmaxf(s[nt][2], s[nt][3]));
        }
        mt0 = fmaxf(mt0, __shfl_xor_sync(0xffffffffu, mt0, 1));
        mt0 = fmaxf(mt0, __shfl_xor_sync(0xffffffffu, mt0, 2));
        mt1 = fmaxf(mt1, __shfl_xor_sync(0xffffffffu, mt1, 1));
        mt1 = fmaxf(mt1, __shfl_xor_sync(0xffffffffu, mt1, 2));
        const float mn0 = fmaxf(m0, mt0), mn1 = fmaxf(m1, mt1);
        const float c0 = exp2f((m0 - mn0) * LOG2E);
        const float c1 = exp2f((m1 - mn1) * LOG2E);
        m0 = mn0; m1 = mn1;
        float ps0 = 0.f, ps1 = 0.f;
        #pragma unroll
        for (int nt = 0; nt < 8; nt++) {
            s[nt][0] = exp2f((s[nt][0] - mn0) * LOG2E);
            s[nt][1] = exp2f((s[nt][1] - mn0) * LOG2E);
            s[nt][2] = exp2f((s[nt][2] - mn1) * LOG2E);
            s[nt][3] = exp2f((s[nt][3] - mn1) * LOG2E);
            ps0 += s[nt][0] + s[nt][1];
            ps1 += s[nt][2] + s[nt][3];
        }
        ps0 += __shfl_xor_sync(0xffffffffu, ps0, 1);
        ps0 += __shfl_xor_sync(0xffffffffu, ps0, 2);
        ps1 += __shfl_xor_sync(0xffffffffu, ps1, 1);
        ps1 += __shfl_xor_sync(0xffffffffu, ps1, 2);
        l0 = l0 * c0 + ps0;
        l1 = l1 * c1 + ps1;
        #pragma unroll
        for (int et = 0; et < 8; et++) {
            o[et][0] *= c0; o[et][1] *= c0;
            o[et][2] *= c1; o[et][3] *= c1;
        }

        // ---- O += P @ V  (P split hi/lo fp16, V single) ----
        #pragma unroll
        for (int ka = 0; ka < 4; ka++) {
            uint32_t ah[4], al[4];
            {
                const float* pa = s[2 * ka];
                const float* pb = s[2 * ka + 1];
                split2(pa[0], pa[1], ah[0], al[0]);
                split2(pa[2], pa[3], ah[1], al[1]);
                split2(pb[0], pb[1], ah[2], al[2]);
                split2(pb[2], pb[3], ah[3], al[3]);
            }
            #pragma unroll
            for (int p = 0; p < 4; p++) {
                uint32_t off = (uint32_t)(p*16*AST + ka*16 + laneB) * 2;
                uint32_t th[4];
                ldsm4(th, vbB + off);
                mma16816(o[2*p],   ah, th);
                mma16816(o[2*p],   al, th);
                mma16816(o[2*p+1], ah, th + 2);
                mma16816(o[2*p+1], al, th + 2);
            }
        }
        __syncthreads();
    }

    // epilogue: normalize, split hi/lo fp16, write [b][s][h*HD + e]
    const float inv0 = 1.0f / l0, inv1 = 1.0f / l1;
    const int b = bh >> 4, h = bh & 15;
    const int s0 = qt * 64 + r0w + g, s1 = s0 + 8;
    const size_t base0 = ((size_t)b * SS + s0) * DD + h * HD;
    const size_t base1 = ((size_t)b * SS + s1) * DD + h * HD;
    #pragma unroll
    for (int et = 0; et < 8; et++) {
        int e = et * 8 + t2;
        uint32_t h01, l01, h23, l23;
        split2(o[et][0] * inv0, o[et][1] * inv0, h01, l01);
        split2(o[et][2] * inv1, o[et][3] * inv1, h23, l23);
        *(uint32_t*)(g_Ah + base0 + e) = h01;
        *(uint32_t*)(g_Ah + base1 + e) = h23;
        *(uint32_t*)(g_Al + base0 + e) = l01;
        *(uint32_t*)(g_Al + base1 + e) = l23;
    }
}

// ================= Kernel C: output projection (fp16 2-term) =================
__global__ __launch_bounds__(256) void proj_gemm(
    const float* __restrict__ bp, float* __restrict__ out)
{
    extern __shared__ __half sm[];
    const uint32_t sb = s2u(sm);
    const int tid = threadIdx.x, lane = tid & 31, wid = tid >> 5;
    const int wm = wid & 3, wn = wid >> 2;
    const int j0 = blockIdx.x * 64, m0 = blockIdx.y * 128;

    auto issue = [&](int c, int st) {
        const uint32_t base = sb + (uint32_t)st * (ST_ELEMS * 2);
        const int k0 = c * 64;
        #pragma unroll
        for (int i = 0; i < 4; i++) {
            int idx = tid + i * 256;
            int row = idx >> 3, qq = idx & 7;
            size_t go = (size_t)(m0 + row) * DD + k0 + qq * 8;
            uint32_t so = (uint32_t)(row * AST + qq * 8) * 2;
            cpa16(base + ST_AH * 2 + so, g_Ah + go);
            cpa16(base + ST_AL * 2 + so, g_Al + go);
        }
        #pragma unroll
        for (int i = 0; i < 2; i++) {
            int idx = tid + i * 256;
            int row = idx >> 3, qq = idx & 7;
            size_t go = (size_t)(j0 + row) * DD + k0 + qq * 8;
            uint32_t so = (uint32_t)(row * AST + qq * 8) * 2;
            cpa16(base + ST_B * 2 + so, g_P + go);
        }
        asm volatile("cp.async.commit_group;" ::: "memory");
    };

    float d[2][4][4] = {};
    const int g = lane >> 2, t2 = (lane & 3) * 2;
    const int rr = lane & 7, q8 = lane >> 3;
    const int laneA = (rr + ((q8 & 1) ? 8 : 0)) * AST + ((q8 & 2) ? 8 : 0);
    const int laneB = (rr + ((q8 & 2) ? 8 : 0)) * AST + ((q8 & 1) ? 8 : 0);

    issue(0, 0);
    for (int c = 0; c < 16; c++) {
        const int st = c & 1;
        if (c < 15) {
            issue(c + 1, st ^ 1);
            asm volatile("cp.async.wait_group 1;" ::: "memory");
        } else {
            asm volatile("cp.async.wait_group 0;" ::: "memory");
        }
        __syncthreads();

        const uint32_t stb = sb + (uint32_t)st * (ST_ELEMS * 2);

        #pragma unroll
        for (int ka = 0; ka < 4; ka++) {
            uint32_t ah[2][4], al[2][4], bh[4][2];
            #pragma unroll
            for (int ma = 0; ma < 2; ma++) {
                uint32_t ao = stb + (uint32_t)(ST_AH + (wm*32 + ma*16)*AST + ka*16 + laneA) * 2;
                ldsm4(ah[ma], ao);
                ldsm4(al[ma], ao + (uint32_t)(ST_AL - ST_AH) * 2);
            }
            #pragma unroll
            for (int p = 0; p < 2; p++) {
                uint32_t bo = stb + (uint32_t)(ST_B + (wn*32 + p*16)*AST + ka*16 + laneB) * 2;
                uint32_t t[4];
                ldsm4(t, bo);
                bh[2*p][0] = t[0]; bh[2*p][1] = t[1]; bh[2*p+1][0] = t[2]; bh[2*p+1][1] = t[3];
            }
            #pragma unroll
            for (int ma = 0; ma < 2; ma++)
                #pragma unroll
                for (int na = 0; na < 4; na++) {
                    mma16816(d[ma][na], ah[ma], bh[na]);
                    mma16816(d[ma][na], al[ma], bh[na]);
                }
        }
        __syncthreads();
    }

    #pragma unroll
    for (int ma = 0; ma < 2; ma++) {
        #pragma unroll
        for (int na = 0; na < 4; na++) {
            int col = j0 + wn * 32 + na * 8 + t2;
            float b0v = bp[col], b1v = bp[col + 1];
            int r0g = m0 + wm * 32 + ma * 16 + g;
            *(float2*)&out[(size_t)r0g * DD + col] =
                make_float2(d[ma][na][0] + b0v, d[ma][na][1] + b1v);
            *(float2*)&out[(size_t)(r0g + 8) * DD + col] =
                make_float2(d[ma][na][2] + b0v, d[ma][na][3] + b1v);
        }
    }
}

// ================= launch =================
extern "C" void kernel_launch(void* const* d_in, const int* in_sizes, int n_in,
                              void* d_out, int out_size)
{
    const float* x  = (const float*)d_in[0];
    const float* Wq = (const float*)d_in[1];
    const float* Wk = (const float*)d_in[2];
    const float* Wv = (const float*)d_in[3];
    const float* Wp = (const float*)d_in[4];
    const float* bp = (const float*)d_in[5];
    float* out = (float*)d_out;

    cudaFuncSetAttribute(qkv_gemm,  cudaFuncAttributeMaxDynamicSharedMemorySize, GEMM_SMEM);
    cudaFuncSetAttribute(proj_gemm, cudaFuncAttributeMaxDynamicSharedMemorySize, GEMM_SMEM);
    cudaFuncSetAttribute(attn_mma,  cudaFuncAttributeMaxDynamicSharedMemorySize, ATT_SMEM);

    prep_x<<<4096, 256>>>(x);
    prep_wqkv<<<dim3(16, 16, 3), 256>>>(Wq, Wk, Wv);
    prep_wp<<<1024, 256>>>(Wp);

    qkv_gemm<<<dim3(32, 48), 256, GEMM_SMEM>>>();
    vprep<<<dim3(32, 32), 256>>>();

    attn_mma<<<dim3(32, 32), 128, ATT_SMEM>>>();

    proj_gemm<<<dim3(16, 32), 256, GEMM_SMEM>>>(bp, out);
}

// round 17
// speedup vs baseline: 1.6126x; 1.6126x over previous
#include <cuda_runtime.h>
#include <cuda_fp16.h>
#include <cstdint>

#define BB 2
#define SS 2048
#define DD 1024
#define HH 16
#define HD 64
#define SCALE 0.03125f   // 1/sqrt(1024)
#define MT   4096        // B*S total rows
#define LOG2E 1.44269504f

// ---------------- scratch (no allocation allowed) ----------------
__device__ __half g_Q [(size_t)BB*HH*SS*HD];   // Q single fp16 (pre-scaled)
__device__ __half g_Kh[(size_t)BB*HH*SS*HD];   // K single fp16
__device__ float  g_V [(size_t)BB*HH*SS*HD];   // fp32 staging [bh][s][e]
__device__ __half g_Vt[(size_t)BB*HH*HD*SS];   // V^T single fp16 [bh][e][s]
__device__ __half g_Xh[(size_t)MT*DD];
__device__ __half g_Xl[(size_t)MT*DD];
__device__ __half g_Ah[(size_t)MT*DD];
__device__ __half g_Al[(size_t)MT*DD];
// qkv weights, pre-transposed, single fp16: [w(q,k,v)][h][n=HD][k=DD]
__device__ __half g_W[(size_t)3*HH*HD*DD];
__device__ __half g_P[(size_t)DD*DD];          // Wp [j][k] single fp16

__device__ __forceinline__ uint32_t h2u(__half2 v) {
    return *reinterpret_cast<uint32_t*>(&v);
}
__device__ __forceinline__ uint32_t s2u(const void* p) {
    uint32_t a;
    asm("{ .reg .u64 t; cvta.to.shared.u64 t, %1; cvt.u32.u64 %0, t; }" : "=r"(a) : "l"(p));
    return a;
}
__device__ __forceinline__ void cpa16(uint32_t dst, const void* src) {
    asm volatile("cp.async.ca.shared.global [%0], [%1], 16;" :: "r"(dst), "l"(src));
}
__device__ __forceinline__ void mma16816(float* d, const uint32_t* a, const uint32_t* b) {
    asm volatile(
        "mma.sync.aligned.m16n8k16.row.col.f32.f16.f16.f32 "
        "{%0,%1,%2,%3},{%4,%5,%6,%7},{%8,%9},{%0,%1,%2,%3};"
        : "+f"(d[0]), "+f"(d[1]), "+f"(d[2]), "+f"(d[3])
        : "r"(a[0]), "r"(a[1]), "r"(a[2]), "r"(a[3]), "r"(b[0]), "r"(b[1]));
}
__device__ __forceinline__ void ldsm4(uint32_t* r, uint32_t a) {
    asm volatile("ldmatrix.sync.aligned.m8n8.x4.shared.b16 {%0,%1,%2,%3}, [%4];"
                 : "=r"(r[0]), "=r"(r[1]), "=r"(r[2]), "=r"(r[3]) : "r"(a));
}
__device__ __forceinline__ void split2(float f0, float f1, uint32_t& hi, uint32_t& lo) {
    __half2 h = __floats2half2_rn(f0, f1);
    __half2 l = __floats2half2_rn(f0 - __low2float(h), f1 - __high2float(h));
    hi = h2u(h); lo = h2u(l);
}

// ================= prep kernels =====================
__global__ __launch_bounds__(256) void prep_x(const float* __restrict__ x)
{
    size_t i = (size_t)blockIdx.x * 256 + threadIdx.x;
    float4 v = ((const float4*)x)[i];
    uint32_t h01, l01, h23, l23;
    split2(v.x, v.y, h01, l01);
    split2(v.z, v.w, h23, l23);
    ((uint2*)g_Xh)[i] = make_uint2(h01, h23);
    ((uint2*)g_Xl)[i] = make_uint2(l01, l23);
}

// Wq/Wk/Wv: [h][k=1024][n=64] -> g_W: [w][h][n][k] single fp16
__global__ __launch_bounds__(256) void prep_wqkv(
    const float* __restrict__ Wq, const float* __restrict__ Wk, const float* __restrict__ Wv)
{
    __shared__ float ws[64][65];
    const int k0t = blockIdx.x, h = blockIdx.y, w = blockIdx.z;
    const float* W = (w == 0 ? Wq : w == 1 ? Wk : Wv)
                     + (size_t)h * DD * HD + (size_t)k0t * 64 * HD;
    const int tid = threadIdx.x;
    #pragma unroll
    for (int i = 0; i < 4; i++) {
        int idx = tid + i * 256; int kk = idx >> 4, c4 = idx & 15;
        float4 v = *(const float4*)(W + (size_t)kk * HD + c4 * 4);
        ws[kk][c4*4+0] = v.x; ws[kk][c4*4+1] = v.y;
        ws[kk][c4*4+2] = v.z; ws[kk][c4*4+3] = v.w;
    }
    __syncthreads();
    __half* oh = g_W + ((size_t)(w * HH + h) * HD) * DD + k0t * 64;
    #pragma unroll
    for (int i = 0; i < 4; i++) {
        int idx = tid + i * 256; int n = idx >> 4, u = idx & 15;
        __half2 h01 = __floats2half2_rn(ws[u*4+0][n], ws[u*4+1][n]);
        __half2 h23 = __floats2half2_rn(ws[u*4+2][n], ws[u*4+3][n]);
        *(uint2*)(oh + (size_t)n * DD + u * 4) = make_uint2(h2u(h01), h2u(h23));
    }
}

__global__ __launch_bounds__(256) void prep_wp(const float* __restrict__ Wp)
{
    size_t i = (size_t)blockIdx.x * 256 + threadIdx.x;
    float4 v = ((const float4*)Wp)[i];
    __half2 h01 = __floats2half2_rn(v.x, v.y);
    __half2 h23 = __floats2half2_rn(v.z, v.w);
    ((uint2*)g_P)[i] = make_uint2(h2u(h01), h2u(h23));
}

// V fp32 [bh][s][e] -> transposed single fp16 g_Vt [bh][e][s]
__global__ __launch_bounds__(256) void vprep()
{
    __shared__ float ts[64][65];
    const int stile = blockIdx.x, bh = blockIdx.y;
    const int tid = threadIdx.x;
    const float* src = g_V + ((size_t)bh * SS + (size_t)stile * 64) * HD;
    #pragma unroll
    for (int i = 0; i < 4; i++) {
        int idx = tid + i * 256; int row = idx >> 4, c4 = idx & 15;
        float4 v = *(const float4*)(src + (size_t)row * HD + c4 * 4);
        ts[row][c4*4+0] = v.x; ts[row][c4*4+1] = v.y;
        ts[row][c4*4+2] = v.z; ts[row][c4*4+3] = v.w;
    }
    __syncthreads();
    #pragma unroll
    for (int i = 0; i < 4; i++) {
        int idx = tid + i * 256; int e = idx >> 4, c4 = idx & 15;
        __half2 h01 = __floats2half2_rn(ts[c4*4+0][e], ts[c4*4+1][e]);
        __half2 h23 = __floats2half2_rn(ts[c4*4+2][e], ts[c4*4+3][e]);
        size_t d = ((size_t)bh * HD + e) * SS + (size_t)stile * 64 + c4 * 4;
        *(uint2*)(g_Vt + d) = make_uint2(h2u(h01), h2u(h23));
    }
}

// =============== GEMM smem layout: 2-stage pipeline ==========================
#define AST 72
#define ST_AH 0
#define ST_AL (128*AST)
#define ST_B  (2*128*AST)
#define ST_ELEMS (2*128*AST + 64*AST)   // 23040
#define GEMM_SMEM (2*ST_ELEMS*2)        // 92160 bytes

// ================= Kernel A: QKV GEMM, specialized (no runtime branch) =======
// NEED_AL=false: Q/K 1-term.  NEED_AL=true: V 2-term.
// grid (32 m-tiles, n-tiles), block 256 (8 warps, 4m x 2n).
template<bool NEED_AL, int O_BASE>
__global__ __launch_bounds__(256) void qkv_gemm_t(void)
{
    extern __shared__ __half sm[];
    const uint32_t sb = s2u(sm);
    const int tid = threadIdx.x, lane = tid & 31, wid = tid >> 5;
    const int wm = wid & 3, wn = wid >> 2;
    const int m0 = blockIdx.x * 128;
    const int nt = O_BASE * 16 + blockIdx.y;   // global {o,h} index
    const int o = nt >> 4, h = nt & 15;

    const __half* W = g_W + (size_t)nt * HD * DD;

    auto issue = [&](int c, int st) {
        const uint32_t base = sb + (uint32_t)st * (ST_ELEMS * 2);
        const int k0 = c * 64;
        #pragma unroll
        for (int i = 0; i < 4; i++) {
            int idx = tid + i * 256;
            int row = idx >> 3, qq = idx & 7;
            size_t go = (size_t)(m0 + row) * DD + k0 + qq * 8;
            uint32_t so = (uint32_t)(row * AST + qq * 8) * 2;
            cpa16(base + ST_AH * 2 + so, g_Xh + go);
            if (NEED_AL) cpa16(base + ST_AL * 2 + so, g_Xl + go);
        }
        #pragma unroll
        for (int i = 0; i < 2; i++) {
            int idx = tid + i * 256;
            int row = idx >> 3, qq = idx & 7;
            size_t go = (size_t)row * DD + k0 + qq * 8;
            uint32_t so = (uint32_t)(row * AST + qq * 8) * 2;
            cpa16(base + ST_B * 2 + so, W + go);
        }
        asm volatile("cp.async.commit_group;" ::: "memory");
    };

    float d[2][4][4] = {};
    const int g = lane >> 2, t2 = (lane & 3) * 2;
    const int rr = lane & 7, q8 = lane >> 3;
    const int laneA = (rr + ((q8 & 1) ? 8 : 0)) * AST + ((q8 & 2) ? 8 : 0);
    const int laneB = (rr + ((q8 & 2) ? 8 : 0)) * AST + ((q8 & 1) ? 8 : 0);

    issue(0, 0);
    for (int c = 0; c < 16; c++) {
        const int st = c & 1;
        if (c < 15) {
            issue(c + 1, st ^ 1);
            asm volatile("cp.async.wait_group 1;" ::: "memory");
        } else {
            asm volatile("cp.async.wait_group 0;" ::: "memory");
        }
        __syncthreads();

        const uint32_t stb = sb + (uint32_t)st * (ST_ELEMS * 2);

        #pragma unroll
        for (int ka = 0; ka < 4; ka++) {
            uint32_t ah[2][4], al[2][4], bh[4][2];
            #pragma unroll
            for (int ma = 0; ma < 2; ma++) {
                uint32_t ao = stb + (uint32_t)(ST_AH + (wm*32 + ma*16)*AST + ka*16 + laneA) * 2;
                ldsm4(ah[ma], ao);
                if (NEED_AL) ldsm4(al[ma], ao + (uint32_t)(ST_AL - ST_AH) * 2);
            }
            #pragma unroll
            for (int p = 0; p < 2; p++) {
                uint32_t bo = stb + (uint32_t)(ST_B + (wn*32 + p*16)*AST + ka*16 + laneB) * 2;
                uint32_t t[4];
                ldsm4(t, bo);
                bh[2*p][0] = t[0]; bh[2*p][1] = t[1]; bh[2*p+1][0] = t[2]; bh[2*p+1][1] = t[3];
            }
            #pragma unroll
            for (int ma = 0; ma < 2; ma++)
                #pragma unroll
                for (int na = 0; na < 4; na++) {
                    mma16816(d[ma][na], ah[ma], bh[na]);
                    if (NEED_AL) mma16816(d[ma][na], al[ma], bh[na]);
                }
        }
        __syncthreads();
    }

    // epilogue: Q -> single fp16 (pre-scaled); K -> single fp16; V -> fp32
    const float sc = (o == 0) ? SCALE : 1.0f;
    #pragma unroll
    for (int ma = 0; ma < 2; ma++) {
        #pragma unroll
        for (int na = 0; na < 4; na++) {
            int col = wn * 32 + na * 8 + t2;
            int r0g = m0 + wm * 32 + ma * 16 + g;
            int b0 = r0g >> 11, s0 = r0g & 2047;
            int r1g = r0g + 8;
            int b1 = r1g >> 11, s1 = r1g & 2047;
            size_t a0 = (((size_t)(b0 * HH + h)) * SS + s0) * HD + col;
            size_t a1 = (((size_t)(b1 * HH + h)) * SS + s1) * HD + col;
            if (NEED_AL) {           // o == 2: V output, fp32
                *(float2*)&g_V[a0] = make_float2(d[ma][na][0], d[ma][na][1]);
                *(float2*)&g_V[a1] = make_float2(d[ma][na][2], d[ma][na][3]);
            } else {
                __half* G = (o == 0) ? g_Q : g_Kh;
                __half2 h01 = __floats2half2_rn(d[ma][na][0] * sc, d[ma][na][1] * sc);
                __half2 h23 = __floats2half2_rn(d[ma][na][2] * sc, d[ma][na][3] * sc);
                *(uint32_t*)(G + a0) = h2u(h01);
                *(uint32_t*)(G + a1) = h2u(h23);
            }
        }
    }
}

// ================= Kernel B: flash attention ================================
// Q single fp16; QK 1-term; PV 2-term (P hi/lo).
// smem: Q (64x72 = 9216 B) + 2 stages x (K + V tiles, 18432 B) = 46080 B
#define QB       9216
#define KTILE_B  9216
#define ASTAGE_B 18432
#define ATT_SMEM (QB + 2*ASTAGE_B)

__global__ __launch_bounds__(128) void attn_mma()
{
    extern __shared__ __half smb[];
    const uint32_t sb = s2u(smb);
    const int tid = threadIdx.x, lane = tid & 31, wid = tid >> 5;
    const int g = lane >> 2, t2 = (lane & 3) * 2;
    const int qt = 31 - blockIdx.x;
    const int bh = blockIdx.y;
    const int r0w = wid * 16;

    const int rr = lane & 7, q8 = lane >> 3;
    const int laneA = (rr + ((q8 & 1) ? 8 : 0)) * AST + ((q8 & 2) ? 8 : 0);
    const int laneB = (rr + ((q8 & 2) ? 8 : 0)) * AST + ((q8 & 1) ? 8 : 0);

    __half* Qs = smb;

    // Q tile load: 64 rows x 8 uint4
    {
        const __half* sh = g_Q + ((size_t)bh * SS + (size_t)qt * 64) * HD;
        #pragma unroll
        for (int i = 0; i < 4; i++) {
            int idx = tid + i * 128; int row = idx >> 3, qq = idx & 7;
            *(uint4*)&Qs[row * AST + qq * 8] = *(const uint4*)(sh + (size_t)row * HD + qq * 8);
        }
    }

    auto issue = [&](int j, int st) {
        const uint32_t base = sb + QB + st * ASTAGE_B;
        const __half* kh = g_Kh + ((size_t)bh * SS + (size_t)j * 64) * HD;
        const __half* vv = g_Vt + (size_t)bh * HD * SS + (size_t)j * 64;
        #pragma unroll
        for (int i = 0; i < 4; i++) {
            int idx = tid + i * 128; int row = idx >> 3, qq = idx & 7;
            uint32_t so = (uint32_t)(row * AST + qq * 8) * 2;
            cpa16(base + so, kh + (size_t)row * HD + qq * 8);
            cpa16(base + KTILE_B + so, vv + (size_t)row * SS + qq * 8);
        }
        asm volatile("cp.async.commit_group;" ::: "memory");
    };

    float m0 = -1e30f, m1 = -1e30f, l0 = 0.f, l1 = 0.f;
    float o[8][4] = {};

    issue(0, 0);

    for (int j = 0; j <= qt; j++) {
        const int st = j & 1;
        if (j < qt) {
            issue(j + 1, st ^ 1);
            asm volatile("cp.async.wait_group 1;" ::: "memory");
        } else {
            asm volatile("cp.async.wait_group 0;" ::: "memory");
        }
        __syncthreads();

        const uint32_t kbB = sb + QB + st * ASTAGE_B;
        const uint32_t vbB = kbB + KTILE_B;

        // ---- S = Q @ K^T (1-term) ----
        float s[8][4] = {};
        #pragma unroll
        for (int ka = 0; ka < 4; ka++) {
            uint32_t qh[4];
            uint32_t qo = sb + (uint32_t)(r0w * AST + ka*16 + laneA) * 2;
            ldsm4(qh, qo);
            #pragma unroll
            for (int p = 0; p < 4; p++) {
                uint32_t off = (uint32_t)(p*16*AST + ka*16 + laneB) * 2;
                uint32_t th[4];
                ldsm4(th, kbB + off);
                mma16816(s[2*p],   qh, th);
                mma16816(s[2*p+1], qh, th + 2);
            }
        }

        if (j == qt) {
            const int row0 = r0w + g, row1 = row0 + 8;
            #pragma unroll
            for (int nt = 0; nt < 8; nt++) {
                int cb = nt * 8 + t2;
                if (cb     > row0) s[nt][0] = -1e30f;
                if (cb + 1 > row0) s[nt][1] = -1e30f;
                if (cb     > row1) s[nt][2] = -1e30f;
                if (cb + 1 > row1) s[nt][3] = -1e30f;
            }
        }

        float mt0 = -1e30f, mt1 = -1e30f;
        #pragma unroll
        for (int nt = 0; nt < 8; nt++) {
            mt0 = fmaxf(mt0, fmaxf(s[nt][0], s[nt][1]));
            mt1 = fmaxf(mt1, fmaxf(s[nt][2], s[nt][3]));
        }
        mt0 = fmaxf(mt0, __shfl_xor_sync(0xffffffffu, mt0, 1));
        mt0 = fmaxf(mt0, __shfl_xor_sync(0xffffffffu, mt0, 2));
        mt1 = fmaxf(mt1, __shfl_xor_sync(0xffffffffu, mt1, 1));
        mt1 = fmaxf(mt1, __shfl_xor_sync(0xffffffffu, mt1, 2));
        const float mn0 = fmaxf(m0, mt0), mn1 = fmaxf(m1, mt1);
        const float c0 = exp2f((m0 - mn0) * LOG2E);
        const float c1 = exp2f((m1 - mn1) * LOG2E);
        m0 = mn0; m1 = mn1;
        float ps0 = 0.f, ps1 = 0.f;
        #pragma unroll
        for (int nt = 0; nt < 8; nt++) {
            s[nt][0] = exp2f((s[nt][0] - mn0) * LOG2E);
            s[nt][1] = exp2f((s[nt][1] - mn0) * LOG2E);
            s[nt][2] = exp2f((s[nt][2] - mn1) * LOG2E);
            s[nt][3] = exp2f((s[nt][3] - mn1) * LOG2E);
            ps0 += s[nt][0] + s[nt][1];
            ps1 += s[nt][2] + s[nt][3];
        }
        ps0 += __shfl_xor_sync(0xffffffffu, ps0, 1);
        ps0 += __shfl_xor_sync(0xffffffffu, ps0, 2);
        ps1 += __shfl_xor_sync(0xffffffffu, ps1, 1);
        ps1 += __shfl_xor_sync(0xffffffffu, ps1, 2);
        l0 = l0 * c0 + ps0;
        l1 = l1 * c1 + ps1;
        #pragma unroll
        for (int et = 0; et < 8; et++) {
            o[et][0] *= c0; o[et][1] *= c0;
            o[et][2] *= c1; o[et][3] *= c1;
        }

        // ---- O += P @ V  (P split hi/lo fp16, V single) ----
        #pragma unroll
        for (int ka = 0; ka < 4; ka++) {
            uint32_t ah[4], al[4];
            {
                const float* pa = s[2 * ka];
                const float* pb = s[2 * ka + 1];
                split2(pa[0], pa[1], ah[0], al[0]);
                split2(pa[2], pa[3], ah[1], al[1]);
                split2(pb[0], pb[1], ah[2], al[2]);
                split2(pb[2], pb[3], ah[3], al[3]);
            }
            #pragma unroll
            for (int p = 0; p < 4; p++) {
                uint32_t off = (uint32_t)(p*16*AST + ka*16 + laneB) * 2;
                uint32_t th[4];
                ldsm4(th, vbB + off);
                mma16816(o[2*p],   ah, th);
                mma16816(o[2*p],   al, th);
                mma16816(o[2*p+1], ah, th + 2);
                mma16816(o[2*p+1], al, th + 2);
            }
        }
        __syncthreads();
    }

    // epilogue: normalize, split hi/lo fp16, write [b][s][h*HD + e]
    const float inv0 = 1.0f / l0, inv1 = 1.0f / l1;
    const int b = bh >> 4, h = bh & 15;
    const int s0 = qt * 64 + r0w + g, s1 = s0 + 8;
    const size_t base0 = ((size_t)b * SS + s0) * DD + h * HD;
    const size_t base1 = ((size_t)b * SS + s1) * DD + h * HD;
    #pragma unroll
    for (int et = 0; et < 8; et++) {
        int e = et * 8 + t2;
        uint32_t h01, l01, h23, l23;
        split2(o[et][0] * inv0, o[et][1] * inv0, h01, l01);
        split2(o[et][2] * inv1, o[et][3] * inv1, h23, l23);
        *(uint32_t*)(g_Ah + base0 + e) = h01;
        *(uint32_t*)(g_Ah + base1 + e) = h23;
        *(uint32_t*)(g_Al + base0 + e) = l01;
        *(uint32_t*)(g_Al + base1 + e) = l23;
    }
}

// ================= Kernel C: output projection (fp16 2-term) =================
__global__ __launch_bounds__(256) void proj_gemm(
    const float* __restrict__ bp, float* __restrict__ out)
{
    extern __shared__ __half sm[];
    const uint32_t sb = s2u(sm);
    const int tid = threadIdx.x, lane = tid & 31, wid = tid >> 5;
    const int wm = wid & 3, wn = wid >> 2;
    const int j0 = blockIdx.x * 64, m0 = blockIdx.y * 128;

    auto issue = [&](int c, int st) {
        const uint32_t base = sb + (uint32_t)st * (ST_ELEMS * 2);
        const int k0 = c * 64;
        #pragma unroll
        for (int i = 0; i < 4; i++) {
            int idx = tid + i * 256;
            int row = idx >> 3, qq = idx & 7;
            size_t go = (size_t)(m0 + row) * DD + k0 + qq * 8;
            uint32_t so = (uint32_t)(row * AST + qq * 8) * 2;
            cpa16(base + ST_AH * 2 + so, g_Ah + go);
            cpa16(base + ST_AL * 2 + so, g_Al + go);
        }
        #pragma unroll
        for (int i = 0; i < 2; i++) {
            int idx = tid + i * 256;
            int row = idx >> 3, qq = idx & 7;
            size_t go = (size_t)(j0 + row) * DD + k0 + qq * 8;
            uint32_t so = (uint32_t)(row * AST + qq * 8) * 2;
            cpa16(base + ST_B * 2 + so, g_P + go);
        }
        asm volatile("cp.async.commit_group;" ::: "memory");
    };

    float d[2][4][4] = {};
    const int g = lane >> 2, t2 = (lane & 3) * 2;
    const int rr = lane & 7, q8 = lane >> 3;
    const int laneA = (rr + ((q8 & 1) ? 8 : 0)) * AST + ((q8 & 2) ? 8 : 0);
    const int laneB = (rr + ((q8 & 2) ? 8 : 0)) * AST + ((q8 & 1) ? 8 : 0);

    issue(0, 0);
    for (int c = 0; c < 16; c++) {
        const int st = c & 1;
        if (c < 15) {
            issue(c + 1, st ^ 1);
            asm volatile("cp.async.wait_group 1;" ::: "memory");
        } else {
            asm volatile("cp.async.wait_group 0;" ::: "memory");
        }
        __syncthreads();

        const uint32_t stb = sb + (uint32_t)st * (ST_ELEMS * 2);

        #pragma unroll
        for (int ka = 0; ka < 4; ka++) {
            uint32_t ah[2][4], al[2][4], bh[4][2];
            #pragma unroll
            for (int ma = 0; ma < 2; ma++) {
                uint32_t ao = stb + (uint32_t)(ST_AH + (wm*32 + ma*16)*AST + ka*16 + laneA) * 2;
                ldsm4(ah[ma], ao);
                ldsm4(al[ma], ao + (uint32_t)(ST_AL - ST_AH) * 2);
            }
            #pragma unroll
            for (int p = 0; p < 2; p++) {
                uint32_t bo = stb + (uint32_t)(ST_B + (wn*32 + p*16)*AST + ka*16 + laneB) * 2;
                uint32_t t[4];
                ldsm4(t, bo);
                bh[2*p][0] = t[0]; bh[2*p][1] = t[1]; bh[2*p+1][0] = t[2]; bh[2*p+1][1] = t[3];
            }
            #pragma unroll
            for (int ma = 0; ma < 2; ma++)
                #pragma unroll
                for (int na = 0; na < 4; na++) {
                    mma16816(d[ma][na], ah[ma], bh[na]);
                    mma16816(d[ma][na], al[ma], bh[na]);
                }
        }
        __syncthreads();
    }

    #pragma unroll
    for (int ma = 0; ma < 2; ma++) {
        #pragma unroll
        for (int na = 0; na < 4; na++) {
            int col = j0 + wn * 32 + na * 8 + t2;
            float b0v = bp[col], b1v = bp[col + 1];
            int r0g = m0 + wm * 32 + ma * 16 + g;
            *(float2*)&out[(size_t)r0g * DD + col] =
                make_float2(d[ma][na][0] + b0v, d[ma][na][1] + b1v);
            *(float2*)&out[(size_t)(r0g + 8) * DD + col] =
                make_float2(d[ma][na][2] + b0v, d[ma][na][3] + b1v);
        }
    }
}

// ================= launch =================
extern "C" void kernel_launch(void* const* d_in, const int* in_sizes, int n_in,
                              void* d_out, int out_size)
{
    const float* x  = (const float*)d_in[0];
    const float* Wq = (const float*)d_in[1];
    const float* Wk = (const float*)d_in[2];
    const float* Wv = (const float*)d_in[3];
    const float* Wp = (const float*)d_in[4];
    const float* bp = (const float*)d_in[5];
    float* out = (float*)d_out;

    cudaFuncSetAttribute(qkv_gemm_t<false, 0>, cudaFuncAttributeMaxDynamicSharedMemorySize, GEMM_SMEM);
    cudaFuncSetAttribute(qkv_gemm_t<true, 2>,  cudaFuncAttributeMaxDynamicSharedMemorySize, GEMM_SMEM);
    cudaFuncSetAttribute(proj_gemm, cudaFuncAttributeMaxDynamicSharedMemorySize, GEMM_SMEM);
    cudaFuncSetAttribute(attn_mma,  cudaFuncAttributeMaxDynamicSharedMemorySize, ATT_SMEM);

    prep_x<<<4096, 256>>>(x);
    prep_wqkv<<<dim3(16, 16, 3), 256>>>(Wq, Wk, Wv);
    prep_wp<<<1024, 256>>>(Wp);

    qkv_gemm_t<false, 0><<<dim3(32, 32), 256, GEMM_SMEM>>>();   // Q and K, 1-term
    qkv_gemm_t<true, 2><<<dim3(32, 16), 256, GEMM_SMEM>>>();    // V, 2-term
    vprep<<<dim3(32, 32), 256>>>();

    attn_mma<<<dim3(32, 32), 128, ATT_SMEM>>>();

    proj_gemm<<<dim3(16, 32), 256, GEMM_SMEM>>>(bp, out);
}